// round 8
// baseline (speedup 1.0000x reference)
#include <cuda_runtime.h>
#include <math.h>

typedef unsigned long long ull;
constexpr int S_ = 500;

// ---------------- device scratch ----------------
__device__ float g_tk[2500];
__device__ float g_at2[1001 * 104];              // duplicated attn pairs [q][2m..2m+1]
__device__ float g_c1[1001 * 100];
__device__ float g_ve[4004 * 200];
__device__ float g_ea[(size_t)4004 * 400];
__device__ float g_wo2[400];
__device__ float g_bo2[4];
__device__ float g_w2m[100];
__device__ float g_b2m[1];
__device__ float g_h[(size_t)512 * 500 * 200];   // read vectors [n][200], n=b*500+t

// ---------------- f32x2 helpers ----------------
#define FMA2(d, a, b, c) \
    asm("fma.rn.f32x2 %0, %1, %2, %3;" : "=l"(d) : "l"(a), "l"(b), "l"(c))
__device__ __forceinline__ ull PK(float x, float y) {
    ull u;
    asm("mov.b64 %0, {%1, %2};" : "=l"(u) : "r"(__float_as_uint(x)), "r"(__float_as_uint(y)));
    return u;
}
__device__ __forceinline__ float HADD(ull u) {
    unsigned lo, hi;
    asm("mov.b64 {%0, %1}, %2;" : "=r"(lo), "=r"(hi) : "l"(u));
    return __uint_as_float(lo) + __uint_as_float(hi);
}
__device__ __forceinline__ void UNPK(float& x, float& y, ull u) {
    unsigned lo, hi;
    asm("mov.b64 {%0, %1}, %2;" : "=r"(lo), "=r"(hi) : "l"(u));
    x = __uint_as_float(lo); y = __uint_as_float(hi);
}
__device__ __forceinline__ void cp16(float* dst, const float* src) {
    unsigned d = (unsigned)__cvta_generic_to_shared(dst);
    asm volatile("cp.async.ca.shared.global [%0], [%1], 16;\n" :: "r"(d), "l"(src));
}

// ---------------- prep kernels ----------------
__global__ void prepA(const float* __restrict__ Wv, const float* __restrict__ bv,
                      const float* __restrict__ qet, const float* __restrict__ W1,
                      const float* __restrict__ b1,
                      const float* __restrict__ km, const float* __restrict__ Wk,
                      const float* __restrict__ bk,
                      const float* __restrict__ W2, const float* __restrict__ b2,
                      const float* __restrict__ Wo, const float* __restrict__ bo) {
    int b = blockIdx.x, tid = threadIdx.x;
    if (b < 3129) {
        int idx = b * 256 + tid;
        if (idx < 4004 * 200) {
            int i = idx / 200, v = idx % 200;
            int q = i >> 2, r = i & 3;
            float acc = bv[v];
            if (q > 0) {
#pragma unroll
                for (int c = 0; c < 4; c++) {
                    float w = 1.0f - fabsf((float)(c - r)) * (1.0f / 3.0f);
                    if (w > 0.0f) acc = fmaf(w, Wv[v * 4000 + c * 1000 + q - 1], acc);
                }
            }
            g_ve[idx] = acc;
        }
    } else if (b < 3521) {
        int idx = (b - 3129) * 256 + tid;
        if (idx < 1001 * 100) {
            int q = idx / 100, j = idx % 100;
            float a = b1[j];
            const float* w = W1 + j * 250 + 200;
            const float* e = qet + q * 50;
            for (int k = 0; k < 50; k++) a = fmaf(w[k], e[k], a);
            g_c1[idx] = a;
        }
    } else if (b < 3531) {
        int i = (b - 3521) * 256 + tid;
        if (i < 2500) {
            int m = i / 50, k = i % 50;
            float a = bk[m];
            for (int l = 0; l < 50; l++) a = fmaf(km[l * 50 + k], Wk[m * 50 + l], a);
            g_tk[i] = a;
        }
    } else {
        int i = (b - 3531) * 256 + tid;
        if (i < 400) {
            int c = i / 100, k = i % 100;
            float a = 0.f;
            for (int f = 0; f < 50; f++) a = fmaf(Wo[c * 50 + f], W2[f * 100 + k], a);
            g_wo2[i] = a;
        } else if (i < 500) {
            int k = i - 400;
            float a = 0.f;
            for (int f = 0; f < 50; f++) a += W2[f * 100 + k];
            g_w2m[k] = a * (1.f / 50.f);
        } else if (i < 504) {
            int c = i - 500;
            float a = bo[c];
            for (int f = 0; f < 50; f++) a = fmaf(Wo[c * 50 + f], b2[f], a);
            g_bo2[c] = a;
        } else if (i == 504) {
            float a = 0.f;
            for (int f = 0; f < 50; f++) a += b2[f];
            g_b2m[0] = a * (1.f / 50.f);
        }
    }
}

__global__ void prepB(const float* __restrict__ qet, const float* __restrict__ Wq,
                      const float* __restrict__ bq) {
    __shared__ float qe[50], qu[50], lg[50], red[2];
    int q = blockIdx.x, tid = threadIdx.x;
    if (tid < 50) qe[tid] = qet[q * 50 + tid];
    __syncthreads();
    if (tid < 50) {
        float a = bq[tid];
        for (int l = 0; l < 50; l++) a = fmaf(Wq[tid * 50 + l], qe[l], a);
        qu[tid] = tanhf(a);
    }
    __syncthreads();
    if (tid < 50) {
        float a = 0.f;
        for (int k = 0; k < 50; k++) a = fmaf(g_tk[tid * 50 + k], qu[k], a);
        lg[tid] = a;
    }
    __syncthreads();
    if (tid == 0) {
        float mx = -1e30f;
        for (int m = 0; m < 50; m++) mx = fmaxf(mx, lg[m]);
        float s = 0.f;
        for (int m = 0; m < 50; m++) s += expf(lg[m] - mx);
        red[0] = mx; red[1] = 1.f / s;
    }
    __syncthreads();
    if (tid < 52) {
        float v = (tid < 50) ? expf(lg[tid] - red[0]) * red[1] : 0.f;
        g_at2[q * 104 + 2 * tid]     = v;
        g_at2[q * 104 + 2 * tid + 1] = v;
    }
}

__global__ void prepC(const float* __restrict__ We, const float* __restrict__ be,
                      const float* __restrict__ Wa, const float* __restrict__ ba) {
    __shared__ float As[16][64];
    __shared__ float Bs[16][64];
    int i0 = blockIdx.x * 64, j0 = blockIdx.y * 64;
    int tid = threadIdx.x;
    int ty = tid >> 4, tx = tid & 15;
    float acc[4][4] = {};
    for (int kb = 0; kb < 200; kb += 16) {
        for (int l = tid; l < 1024; l += 256) {
            int r = l >> 4, c = l & 15;
            int gi = i0 + r, gk = kb + c;
            As[c][r] = (gi < 4004 && gk < 200) ? g_ve[gi * 200 + gk] : 0.f;
            int gj = j0 + r;
            float bval = 0.f;
            if (gj < 400 && gk < 200)
                bval = (gj < 200) ? We[gj * 200 + gk] : Wa[(gj - 200) * 200 + gk];
            Bs[c][r] = bval;
        }
        __syncthreads();
#pragma unroll
        for (int k = 0; k < 16; k++) {
            float a[4], b[4];
#pragma unroll
            for (int u = 0; u < 4; u++) a[u] = As[k][ty * 4 + u];
#pragma unroll
            for (int u = 0; u < 4; u++) b[u] = Bs[k][tx * 4 + u];
#pragma unroll
            for (int u = 0; u < 4; u++)
#pragma unroll
                for (int v = 0; v < 4; v++) acc[u][v] = fmaf(a[u], b[v], acc[u][v]);
        }
        __syncthreads();
    }
#pragma unroll
    for (int u = 0; u < 4; u++) {
        int gi = i0 + ty * 4 + u;
        if (gi >= 4004) break;
#pragma unroll
        for (int v = 0; v < 4; v++) {
            int gj = j0 + tx * 4 + v;
            if (gj >= 400) continue;
            float x = acc[u][v] + ((gj < 200) ? be[gj] : ba[gj - 200]);
            g_ea[(size_t)gi * 400 + gj] = (gj < 200) ? (1.0f / (1.0f + expf(-x))) : tanhf(x);
        }
    }
}

// ================= Phase 1: Vm recurrence, m split across lane pairs ==========
#define TPB1 416
constexpr int G1 = 2;
// smem buf layout (per buf, 1008 floats): [g0 ea 400][g1 ea 400][g0 at2 104][g1 at2 104]
constexpr int P1_QS = 2016;
constexpr int P1_RS = 3016;
constexpr int P1_SMF = 4016;

__device__ __forceinline__ void p1_prefetch(float* buf, const int* qs, const int* rs,
                                            int t1, int i0) {
    for (int i = i0; i < 252; i += 16) {
        if (i < 200) {
            int g = i / 100, j = i % 100;
            int q = qs[g * S_ + t1], r = rs[g * S_ + t1];
            cp16(buf + g * 400 + j * 4, g_ea + (size_t)(q * 4 + r) * 400 + j * 4);
        } else {
            int k = i - 200, g = k / 26, j = k % 26;
            cp16(buf + 800 + g * 104 + j * 4, g_at2 + qs[g * S_ + t1] * 104 + j * 4);
        }
    }
}

__global__ void __launch_bounds__(TPB1, 2)
phase1(const int* __restrict__ questions, const int* __restrict__ responses,
       const float* __restrict__ ivm) {
    __shared__ float sm[P1_SMF];
    int* qs = (int*)(sm + P1_QS);
    int* rs = (int*)(sm + P1_RS);
    const int tid = threadIdx.x;
    const int b0 = blockIdx.x * G1;

    for (int i = tid; i < G1 * S_; i += TPB1) {
        qs[i] = questions[b0 * S_ + i];
        rs[i] = responses[b0 * S_ + i];
    }

    // thread roles: tid<400 compute, tid>=400 prefetch (16 threads)
    const int pp = tid >> 1;          // 0..199
    const int mh = tid & 1;           // m-half
    const int g = (tid < 400) ? pp / 100 : 0;
    const int p = (tid < 400) ? pp % 100 : 0;

    ull vm[25];
    if (tid < 400) {
#pragma unroll
        for (int j = 0; j < 25; j++)
            vm[j] = *(const ull*)(ivm + (mh * 25 + j) * 200 + 2 * p);
    }
    __syncthreads();
    if (tid >= 400) {
        p1_prefetch(sm, qs, rs, 0, tid - 400);
        asm volatile("cp.async.commit_group;\n" ::: "memory");
    }

    size_t hbase = (size_t)(b0 + g) * (S_ * 200) + 2 * p;

    for (int t = 0; t < S_; t++) {
        if (tid >= 400)
            asm volatile("cp.async.wait_group 0;\n" ::: "memory");
        __syncthreads();

        if (tid < 400) {
            const float* tc = sm + (t & 1) * 1008;
            float2 e2 = *(const float2*)(tc + g * 400 + 2 * p);
            float2 a2 = *(const float2*)(tc + g * 400 + 200 + 2 * p);
            ull en = PK(-e2.x, -e2.y), ad = PK(a2.x, a2.y);
            const ull* at2p = (const ull*)(tc + 800 + g * 104) + mh * 25;
            ull ra = 0ull, rb = 0ull;
#pragma unroll
            for (int j = 0; j < 25; j++) {
                ull a = at2p[j];
                ull tt;
                if (j & 1) FMA2(rb, a, vm[j], rb);
                else       FMA2(ra, a, vm[j], ra);
                FMA2(tt, en, vm[j], ad);
                FMA2(vm[j], a, tt, vm[j]);
            }
            ull one2 = PK(1.0f, 1.0f), r2;
            FMA2(r2, rb, one2, ra);
            float rx, ry;
            UNPK(rx, ry, r2);
            unsigned msk = __activemask();
            rx += __shfl_xor_sync(msk, rx, 1);
            ry += __shfl_xor_sync(msk, ry, 1);
            if (mh == 0)
                *(float2*)(g_h + hbase + (size_t)t * 200) = make_float2(rx, ry);
        } else {
            if (t + 1 < S_)
                p1_prefetch(sm + ((t + 1) & 1) * 1008, qs, rs, t + 1, tid - 400);
            asm volatile("cp.async.commit_group;\n" ::: "memory");
        }
    }
}

// ================= Phase 2: batched MLP over all (b,t) =================
#define TPB2 256
constexpr int HSTR = 204;
constexpr int H1STR = 102;
constexpr int O2_H = 0;                       // 64 x 204
constexpr int O2_H1 = 13056;                  // 64 x 102
constexpr int O2_QN = 19584;                  // 64 int
constexpr int P2_SMF = 19648;

__global__ void __launch_bounds__(TPB2, 2)
phase2(const int* __restrict__ questions, const float* __restrict__ W1,
       const float* __restrict__ W2, const float* __restrict__ b2,
       float* __restrict__ outF, float* __restrict__ outM,
       float* __restrict__ outL, float* __restrict__ outP) {
    extern __shared__ float s2[];
    const int tid = threadIdx.x;
    const int n0 = blockIdx.x * 64;
    int* qn = (int*)(s2 + O2_QN);

    for (int i = tid; i < 3200; i += TPB2) {
        int r = i / 50, c = i % 50;
        cp16(s2 + O2_H + r * HSTR + c * 4, g_h + (size_t)(n0 + r) * 200 + c * 4);
    }
    if (tid < 64) qn[tid] = questions[n0 + tid];
    asm volatile("cp.async.commit_group;\n" ::: "memory");
    asm volatile("cp.async.wait_group 0;\n" ::: "memory");
    __syncthreads();

    // h1 = relu(W1[:, :200] @ h + c1[q])
    if (tid < 200) {
        int jg = tid / 8, rg = tid % 8;
        int j0 = jg * 4;
        ull acc[4][8] = {};
        for (int k = 0; k < 200; k += 2) {
            ull h[8];
#pragma unroll
            for (int i = 0; i < 8; i++)
                h[i] = *(const ull*)(s2 + O2_H + (rg + 8 * i) * HSTR + k);
#pragma unroll
            for (int j = 0; j < 4; j++) {
                ull w = *(const ull*)(W1 + (j0 + j) * 250 + k);
#pragma unroll
                for (int i = 0; i < 8; i++) FMA2(acc[j][i], w, h[i], acc[j][i]);
            }
        }
#pragma unroll
        for (int j = 0; j < 4; j++)
#pragma unroll
            for (int i = 0; i < 8; i++) {
                int row = rg + 8 * i;
                float v = HADD(acc[j][i]) + g_c1[qn[row] * 100 + j0 + j];
                s2[O2_H1 + row * H1STR + j0 + j] = fmaxf(v, 0.f);
            }
    }
    __syncthreads();

    // feats (coalesced: consecutive tasks = consecutive f within a row)
    for (int task = tid; task < 3200; task += TPB2) {
        int row = task / 50, f = task % 50;
        ull acc = 0ull;
        const float* h1r = s2 + O2_H1 + row * H1STR;
#pragma unroll
        for (int k2 = 0; k2 < 50; k2++)
            FMA2(acc, *(const ull*)(W2 + f * 100 + 2 * k2),
                 *(const ull*)(h1r + 2 * k2), acc);
        outF[(size_t)(n0 + row) * 50 + f] = HADD(acc) + __ldg(b2 + f);
    }
    // logits + probs
    {
        int row = tid >> 2, c = tid & 3;
        ull acc = 0ull;
        const float* h1r = s2 + O2_H1 + row * H1STR;
#pragma unroll
        for (int k2 = 0; k2 < 50; k2++)
            FMA2(acc, *(const ull*)(g_wo2 + c * 100 + 2 * k2),
                 *(const ull*)(h1r + 2 * k2), acc);
        float lg = HADD(acc) + g_bo2[c];
        float mx = fmaxf(lg, __shfl_xor_sync(0xffffffffu, lg, 1));
        mx = fmaxf(mx, __shfl_xor_sync(0xffffffffu, mx, 2));
        float e = expf(lg - mx);
        float se = e + __shfl_xor_sync(0xffffffffu, e, 1);
        se += __shfl_xor_sync(0xffffffffu, se, 2);
        size_t o = (size_t)(n0 + row) * 4 + c;
        outL[o] = lg;
        outP[o] = e / se;
    }
    // mastery
    if (tid < 64) {
        ull acc = 0ull;
        const float* h1r = s2 + O2_H1 + tid * H1STR;
#pragma unroll
        for (int k2 = 0; k2 < 50; k2++)
            FMA2(acc, *(const ull*)(g_w2m + 2 * k2), *(const ull*)(h1r + 2 * k2), acc);
        outM[n0 + tid] = HADD(acc) + g_b2m[0];
    }
}

// ---------------------------------------------------------------------------

extern "C" void kernel_launch(void* const* d_in, const int* in_sizes, int n_in,
                              void* d_out, int out_size) {
    const int*   questions = (const int*)d_in[0];
    const int*   responses = (const int*)d_in[1];
    const float* qet       = (const float*)d_in[2];
    const float* Wv        = (const float*)d_in[3];
    const float* bv        = (const float*)d_in[4];
    const float* km        = (const float*)d_in[5];
    const float* ivm       = (const float*)d_in[6];
    const float* Wq        = (const float*)d_in[7];
    const float* bq        = (const float*)d_in[8];
    const float* Wk        = (const float*)d_in[9];
    const float* bk        = (const float*)d_in[10];
    const float* We        = (const float*)d_in[11];
    const float* be        = (const float*)d_in[12];
    const float* Wa        = (const float*)d_in[13];
    const float* ba        = (const float*)d_in[14];
    const float* W1        = (const float*)d_in[15];
    const float* b1        = (const float*)d_in[16];
    const float* W2        = (const float*)d_in[17];
    const float* b2        = (const float*)d_in[18];
    const float* Wo        = (const float*)d_in[19];
    const float* bo        = (const float*)d_in[20];

    float* out  = (float*)d_out;
    float* outF = out;
    float* outM = out + (size_t)512 * 500 * 50;
    float* outL = outM + (size_t)512 * 500;
    float* outP = outL + (size_t)512 * 500 * 4;

    cudaFuncSetAttribute(phase2, cudaFuncAttributeMaxDynamicSharedMemorySize,
                         P2_SMF * 4);

    prepA<<<3534, 256>>>(Wv, bv, qet, W1, b1, km, Wk, bk, W2, b2, Wo, bo);
    prepB<<<1001, 64>>>(qet, Wq, bq);
    {
        dim3 grid(63, 7);
        prepC<<<grid, 256>>>(We, be, Wa, ba);
    }
    phase1<<<512 / G1, TPB1>>>(questions, responses, ivm);
    phase2<<<4000, TPB2, P2_SMF * 4>>>(questions, W1, W2, b2,
                                       outF, outM, outL, outP);
}

// round 9
// speedup vs baseline: 1.3791x; 1.3791x over previous
#include <cuda_runtime.h>
#include <math.h>

typedef unsigned long long ull;
constexpr int S_ = 500;

// ---------------- device scratch ----------------
__device__ float g_tk[2500];
__device__ float g_at2[1001 * 104];              // duplicated attn pairs [q][2m..2m+1]
__device__ float g_c1[1001 * 100];
__device__ float g_ve[4004 * 200];
__device__ float g_ea[(size_t)4004 * 400];
__device__ float g_wo2[400];
__device__ float g_bo2[4];
__device__ float g_w2m[100];
__device__ float g_b2m[1];
__device__ float g_h[(size_t)512 * 500 * 200];   // read vectors [b][t][200]

// ---------------- f32x2 helpers ----------------
#define FMA2(d, a, b, c) \
    asm("fma.rn.f32x2 %0, %1, %2, %3;" : "=l"(d) : "l"(a), "l"(b), "l"(c))
__device__ __forceinline__ ull PK(float x, float y) {
    ull u;
    asm("mov.b64 %0, {%1, %2};" : "=l"(u) : "r"(__float_as_uint(x)), "r"(__float_as_uint(y)));
    return u;
}
__device__ __forceinline__ float HADD(ull u) {
    unsigned lo, hi;
    asm("mov.b64 {%0, %1}, %2;" : "=r"(lo), "=r"(hi) : "l"(u));
    return __uint_as_float(lo) + __uint_as_float(hi);
}
__device__ __forceinline__ void cp16(float* dst, const float* src) {
    unsigned d = (unsigned)__cvta_generic_to_shared(dst);
    asm volatile("cp.async.ca.shared.global [%0], [%1], 16;\n" :: "r"(d), "l"(src));
}

// ---------------- prep kernels ----------------
__global__ void prepA(const float* __restrict__ Wv, const float* __restrict__ bv,
                      const float* __restrict__ qet, const float* __restrict__ W1,
                      const float* __restrict__ b1,
                      const float* __restrict__ km, const float* __restrict__ Wk,
                      const float* __restrict__ bk,
                      const float* __restrict__ W2, const float* __restrict__ b2,
                      const float* __restrict__ Wo, const float* __restrict__ bo) {
    int b = blockIdx.x, tid = threadIdx.x;
    if (b < 3129) {
        int idx = b * 256 + tid;
        if (idx < 4004 * 200) {
            int i = idx / 200, v = idx % 200;
            int q = i >> 2, r = i & 3;
            float acc = bv[v];
            if (q > 0) {
#pragma unroll
                for (int c = 0; c < 4; c++) {
                    float w = 1.0f - fabsf((float)(c - r)) * (1.0f / 3.0f);
                    if (w > 0.0f) acc = fmaf(w, Wv[v * 4000 + c * 1000 + q - 1], acc);
                }
            }
            g_ve[idx] = acc;
        }
    } else if (b < 3521) {
        int idx = (b - 3129) * 256 + tid;
        if (idx < 1001 * 100) {
            int q = idx / 100, j = idx % 100;
            float a = b1[j];
            const float* w = W1 + j * 250 + 200;
            const float* e = qet + q * 50;
            for (int k = 0; k < 50; k++) a = fmaf(w[k], e[k], a);
            g_c1[idx] = a;
        }
    } else if (b < 3531) {
        int i = (b - 3521) * 256 + tid;
        if (i < 2500) {
            int m = i / 50, k = i % 50;
            float a = bk[m];
            for (int l = 0; l < 50; l++) a = fmaf(km[l * 50 + k], Wk[m * 50 + l], a);
            g_tk[i] = a;
        }
    } else {
        int i = (b - 3531) * 256 + tid;
        if (i < 400) {
            int c = i / 100, k = i % 100;
            float a = 0.f;
            for (int f = 0; f < 50; f++) a = fmaf(Wo[c * 50 + f], W2[f * 100 + k], a);
            g_wo2[i] = a;
        } else if (i < 500) {
            int k = i - 400;
            float a = 0.f;
            for (int f = 0; f < 50; f++) a += W2[f * 100 + k];
            g_w2m[k] = a * (1.f / 50.f);
        } else if (i < 504) {
            int c = i - 500;
            float a = bo[c];
            for (int f = 0; f < 50; f++) a = fmaf(Wo[c * 50 + f], b2[f], a);
            g_bo2[c] = a;
        } else if (i == 504) {
            float a = 0.f;
            for (int f = 0; f < 50; f++) a += b2[f];
            g_b2m[0] = a * (1.f / 50.f);
        }
    }
}

__global__ void prepB(const float* __restrict__ qet, const float* __restrict__ Wq,
                      const float* __restrict__ bq) {
    __shared__ float qe[50], qu[50], lg[50], red[2];
    int q = blockIdx.x, tid = threadIdx.x;
    if (tid < 50) qe[tid] = qet[q * 50 + tid];
    __syncthreads();
    if (tid < 50) {
        float a = bq[tid];
        for (int l = 0; l < 50; l++) a = fmaf(Wq[tid * 50 + l], qe[l], a);
        qu[tid] = tanhf(a);
    }
    __syncthreads();
    if (tid < 50) {
        float a = 0.f;
        for (int k = 0; k < 50; k++) a = fmaf(g_tk[tid * 50 + k], qu[k], a);
        lg[tid] = a;
    }
    __syncthreads();
    if (tid == 0) {
        float mx = -1e30f;
        for (int m = 0; m < 50; m++) mx = fmaxf(mx, lg[m]);
        float s = 0.f;
        for (int m = 0; m < 50; m++) s += expf(lg[m] - mx);
        red[0] = mx; red[1] = 1.f / s;
    }
    __syncthreads();
    if (tid < 52) {
        float v = (tid < 50) ? expf(lg[tid] - red[0]) * red[1] : 0.f;
        g_at2[q * 104 + 2 * tid]     = v;
        g_at2[q * 104 + 2 * tid + 1] = v;
    }
}

__global__ void prepC(const float* __restrict__ We, const float* __restrict__ be,
                      const float* __restrict__ Wa, const float* __restrict__ ba) {
    __shared__ float As[16][64];
    __shared__ float Bs[16][64];
    int i0 = blockIdx.x * 64, j0 = blockIdx.y * 64;
    int tid = threadIdx.x;
    int ty = tid >> 4, tx = tid & 15;
    float acc[4][4] = {};
    for (int kb = 0; kb < 200; kb += 16) {
        for (int l = tid; l < 1024; l += 256) {
            int r = l >> 4, c = l & 15;
            int gi = i0 + r, gk = kb + c;
            As[c][r] = (gi < 4004 && gk < 200) ? g_ve[gi * 200 + gk] : 0.f;
            int gj = j0 + r;
            float bval = 0.f;
            if (gj < 400 && gk < 200)
                bval = (gj < 200) ? We[gj * 200 + gk] : Wa[(gj - 200) * 200 + gk];
            Bs[c][r] = bval;
        }
        __syncthreads();
#pragma unroll
        for (int k = 0; k < 16; k++) {
            float a[4], b[4];
#pragma unroll
            for (int u = 0; u < 4; u++) a[u] = As[k][ty * 4 + u];
#pragma unroll
            for (int u = 0; u < 4; u++) b[u] = Bs[k][tx * 4 + u];
#pragma unroll
            for (int u = 0; u < 4; u++)
#pragma unroll
                for (int v = 0; v < 4; v++) acc[u][v] = fmaf(a[u], b[v], acc[u][v]);
        }
        __syncthreads();
    }
#pragma unroll
    for (int u = 0; u < 4; u++) {
        int gi = i0 + ty * 4 + u;
        if (gi >= 4004) break;
#pragma unroll
        for (int v = 0; v < 4; v++) {
            int gj = j0 + tx * 4 + v;
            if (gj >= 400) continue;
            float x = acc[u][v] + ((gj < 200) ? be[gj] : ba[gj - 200]);
            g_ea[(size_t)gi * 400 + gj] = (gj < 200) ? (1.0f / (1.0f + expf(-x))) : tanhf(x);
        }
    }
}

// ================= Phase 1: barrier-free Vm recurrence =================
#define TPB1 224
constexpr int G1 = 2;
// smem (floats): [0,1000) qs int | [1000,2000) rs int | [2000,...) per-warp attn bufs
//   warp w, buf d (d=0,1): sm + 2000 + (w*2+d)*208  (g0 at +0, g1 at +104)
constexpr int P1_SMF = 2000 + 7 * 2 * 208;   // 4912 floats

__global__ void __launch_bounds__(TPB1, 2)
phase1(const int* __restrict__ questions, const int* __restrict__ responses,
       const float* __restrict__ ivm) {
    __shared__ float sm[P1_SMF];
    int* qs = (int*)sm;
    int* rs = (int*)(sm + 1000);
    const int tid = threadIdx.x;
    const int wid = tid >> 5, lane = tid & 31;
    const int b0 = blockIdx.x * G1;

    for (int i = tid; i < G1 * S_; i += TPB1) {
        qs[i] = questions[b0 * S_ + i];
        rs[i] = responses[b0 * S_ + i];
    }

    const int cp = (tid < 200) ? tid : 199;   // clamp extra lanes (redundant work)
    const int g = cp / 100, p = cp % 100;

    ull vm[50];
#pragma unroll
    for (int m = 0; m < 50; m++) vm[m] = *(const ull*)(ivm + m * 200 + 2 * p);

    __syncthreads();   // the ONLY block barrier: qs/rs visible

    float* mybuf = sm + 2000 + wid * 416;    // this warp's 2 attn buffers

    // prologue: attn(0) via warp-private cp.async; e/a(0) via plain LDG
    for (int i = lane; i < 52; i += 32) {
        int gg = i / 26, j = i % 26;
        cp16(mybuf + gg * 104 + j * 4, g_at2 + qs[gg * S_] * 104 + j * 4);
    }
    asm volatile("cp.async.commit_group;\n" ::: "memory");

    ull eC, aC;
    {
        int q = qs[g * S_], r = rs[g * S_];
        const float* eb = g_ea + (size_t)(q * 4 + r) * 400;
        eC = *(const ull*)(eb + 2 * p);
        aC = *(const ull*)(eb + 200 + 2 * p);
    }

    size_t hb = (size_t)(b0 + g) * (S_ * 200) + 2 * p;

    for (int t = 0; t < S_; t++) {
        // issue next step's loads first (hidden under this step's compute)
        ull eN = 0ull, aN = 0ull;
        if (t + 1 < S_) {
            int qn = qs[g * S_ + t + 1], rn = rs[g * S_ + t + 1];
            const float* eb = g_ea + (size_t)(qn * 4 + rn) * 400;
            eN = *(const ull*)(eb + 2 * p);
            aN = *(const ull*)(eb + 200 + 2 * p);
            float* nb = mybuf + ((t + 1) & 1) * 208;
            for (int i = lane; i < 52; i += 32) {
                int gg = i / 26, j = i % 26;
                cp16(nb + gg * 104 + j * 4, g_at2 + qs[gg * S_ + t + 1] * 104 + j * 4);
            }
        }
        asm volatile("cp.async.commit_group;\n" ::: "memory");
        asm volatile("cp.async.wait_group 1;\n" ::: "memory");   // group(t) complete
        __syncwarp();

        const ull* at2p = (const ull*)(mybuf + (t & 1) * 208 + g * 104);
        ull en = eC ^ 0x8000000080000000ULL;    // (-e.x, -e.y)
        ull ad = aC;
        ull ra = 0ull, rb = 0ull;
#pragma unroll
        for (int j = 0; j < 50; j++) {
            ull a = at2p[j];
            ull tt;
            if (j & 1) FMA2(rb, a, vm[j], rb);
            else       FMA2(ra, a, vm[j], ra);
            FMA2(tt, en, vm[j], ad);
            FMA2(vm[j], a, tt, vm[j]);
        }
        ull one2 = PK(1.0f, 1.0f), r2;
        FMA2(r2, rb, one2, ra);
        if (tid < 200)
            *(ull*)(g_h + hb + (size_t)t * 200) = r2;
        eC = eN; aC = aN;
    }
}

// ================= Phase 2: batched MLP over all (b,t) =================
#define TPB2 256
constexpr int HSTR = 204;
constexpr int H1STR = 102;
constexpr int O2_H = 0;                       // 64 x 204
constexpr int O2_H1 = 13056;                  // 64 x 102
constexpr int O2_QN = 19584;                  // 64 int
constexpr int P2_SMF = 19648;

__global__ void __launch_bounds__(TPB2, 2)
phase2(const int* __restrict__ questions, const float* __restrict__ W1,
       const float* __restrict__ W2, const float* __restrict__ b2,
       float* __restrict__ outF, float* __restrict__ outM,
       float* __restrict__ outL, float* __restrict__ outP) {
    extern __shared__ float s2[];
    const int tid = threadIdx.x;
    const int n0 = blockIdx.x * 64;
    int* qn = (int*)(s2 + O2_QN);

    for (int i = tid; i < 3200; i += TPB2) {
        int r = i / 50, c = i % 50;
        cp16(s2 + O2_H + r * HSTR + c * 4, g_h + (size_t)(n0 + r) * 200 + c * 4);
    }
    if (tid < 64) qn[tid] = questions[n0 + tid];
    asm volatile("cp.async.commit_group;\n" ::: "memory");
    asm volatile("cp.async.wait_group 0;\n" ::: "memory");
    __syncthreads();

    // h1 = relu(W1[:, :200] @ h + c1[q])
    if (tid < 200) {
        int jg = tid / 8, rg = tid % 8;
        int j0 = jg * 4;
        ull acc[4][8] = {};
        for (int k = 0; k < 200; k += 2) {
            ull h[8];
#pragma unroll
            for (int i = 0; i < 8; i++)
                h[i] = *(const ull*)(s2 + O2_H + (rg + 8 * i) * HSTR + k);
#pragma unroll
            for (int j = 0; j < 4; j++) {
                ull w = *(const ull*)(W1 + (j0 + j) * 250 + k);
#pragma unroll
                for (int i = 0; i < 8; i++) FMA2(acc[j][i], w, h[i], acc[j][i]);
            }
        }
#pragma unroll
        for (int j = 0; j < 4; j++)
#pragma unroll
            for (int i = 0; i < 8; i++) {
                int row = rg + 8 * i;
                float v = HADD(acc[j][i]) + g_c1[qn[row] * 100 + j0 + j];
                s2[O2_H1 + row * H1STR + j0 + j] = fmaxf(v, 0.f);
            }
    }
    __syncthreads();

    // feats (coalesced)
    for (int task = tid; task < 3200; task += TPB2) {
        int row = task / 50, f = task % 50;
        ull acc = 0ull;
        const float* h1r = s2 + O2_H1 + row * H1STR;
#pragma unroll
        for (int k2 = 0; k2 < 50; k2++)
            FMA2(acc, *(const ull*)(W2 + f * 100 + 2 * k2),
                 *(const ull*)(h1r + 2 * k2), acc);
        outF[(size_t)(n0 + row) * 50 + f] = HADD(acc) + __ldg(b2 + f);
    }
    // logits + probs
    {
        int row = tid >> 2, c = tid & 3;
        ull acc = 0ull;
        const float* h1r = s2 + O2_H1 + row * H1STR;
#pragma unroll
        for (int k2 = 0; k2 < 50; k2++)
            FMA2(acc, *(const ull*)(g_wo2 + c * 100 + 2 * k2),
                 *(const ull*)(h1r + 2 * k2), acc);
        float lg = HADD(acc) + g_bo2[c];
        float mx = fmaxf(lg, __shfl_xor_sync(0xffffffffu, lg, 1));
        mx = fmaxf(mx, __shfl_xor_sync(0xffffffffu, mx, 2));
        float e = expf(lg - mx);
        float se = e + __shfl_xor_sync(0xffffffffu, e, 1);
        se += __shfl_xor_sync(0xffffffffu, se, 2);
        size_t o = (size_t)(n0 + row) * 4 + c;
        outL[o] = lg;
        outP[o] = e / se;
    }
    // mastery
    if (tid < 64) {
        ull acc = 0ull;
        const float* h1r = s2 + O2_H1 + tid * H1STR;
#pragma unroll
        for (int k2 = 0; k2 < 50; k2++)
            FMA2(acc, *(const ull*)(g_w2m + 2 * k2), *(const ull*)(h1r + 2 * k2), acc);
        outM[n0 + tid] = HADD(acc) + g_b2m[0];
    }
}

// ---------------------------------------------------------------------------

extern "C" void kernel_launch(void* const* d_in, const int* in_sizes, int n_in,
                              void* d_out, int out_size) {
    const int*   questions = (const int*)d_in[0];
    const int*   responses = (const int*)d_in[1];
    const float* qet       = (const float*)d_in[2];
    const float* Wv        = (const float*)d_in[3];
    const float* bv        = (const float*)d_in[4];
    const float* km        = (const float*)d_in[5];
    const float* ivm       = (const float*)d_in[6];
    const float* Wq        = (const float*)d_in[7];
    const float* bq        = (const float*)d_in[8];
    const float* Wk        = (const float*)d_in[9];
    const float* bk        = (const float*)d_in[10];
    const float* We        = (const float*)d_in[11];
    const float* be        = (const float*)d_in[12];
    const float* Wa        = (const float*)d_in[13];
    const float* ba        = (const float*)d_in[14];
    const float* W1        = (const float*)d_in[15];
    const float* b1        = (const float*)d_in[16];
    const float* W2        = (const float*)d_in[17];
    const float* b2        = (const float*)d_in[18];
    const float* Wo        = (const float*)d_in[19];
    const float* bo        = (const float*)d_in[20];

    float* out  = (float*)d_out;
    float* outF = out;
    float* outM = out + (size_t)512 * 500 * 50;
    float* outL = outM + (size_t)512 * 500;
    float* outP = outL + (size_t)512 * 500 * 4;

    cudaFuncSetAttribute(phase2, cudaFuncAttributeMaxDynamicSharedMemorySize,
                         P2_SMF * 4);

    prepA<<<3534, 256>>>(Wv, bv, qet, W1, b1, km, Wk, bk, W2, b2, Wo, bo);
    prepB<<<1001, 64>>>(qet, Wq, bq);
    {
        dim3 grid(63, 7);
        prepC<<<grid, 256>>>(We, be, Wa, ba);
    }
    phase1<<<512 / G1, TPB1>>>(questions, responses, ivm);
    phase2<<<4000, TPB2, P2_SMF * 4>>>(questions, W1, W2, b2,
                                       outF, outM, outL, outP);
}

// round 10
// speedup vs baseline: 2.2784x; 1.6521x over previous
#include <cuda_runtime.h>
#include <math.h>

typedef unsigned long long ull;
constexpr int S_ = 500;

// ---------------- device scratch ----------------
__device__ float g_at2[1001 * 104];              // duplicated attn pairs [q][2m..2m+1]
__device__ float g_c1[1001 * 100];
__device__ float g_ea[(size_t)4004 * 400];
__device__ float g_w2e[56 * 100];                // [W2(50); Wo@W2(4); colmean W2(1); 0]
__device__ float g_b2e[56];
__device__ float g_h[(size_t)512 * 500 * 200];   // read vectors [b][t][200]

// ---------------- f32x2 helpers ----------------
#define FMA2(d, a, b, c) \
    asm("fma.rn.f32x2 %0, %1, %2, %3;" : "=l"(d) : "l"(a), "l"(b), "l"(c))
__device__ __forceinline__ ull PK(float x, float y) {
    ull u;
    asm("mov.b64 %0, {%1, %2};" : "=l"(u) : "r"(__float_as_uint(x)), "r"(__float_as_uint(y)));
    return u;
}
__device__ __forceinline__ float HADD(ull u) {
    unsigned lo, hi;
    asm("mov.b64 {%0, %1}, %2;" : "=r"(lo), "=r"(hi) : "l"(u));
    return __uint_as_float(lo) + __uint_as_float(hi);
}
__device__ __forceinline__ void cp16(float* dst, const float* src) {
    unsigned d = (unsigned)__cvta_generic_to_shared(dst);
    asm volatile("cp.async.ca.shared.global [%0], [%1], 16;\n" :: "r"(d), "l"(src));
}

// ================= prepBF: attn(+tk inline) | c1 | fold =================
// blocks: [0,1001) attn | [1001,1393) c1 | [1393,1416) fold
__global__ void prepBF(const float* __restrict__ qet, const float* __restrict__ Wq,
                       const float* __restrict__ bq,
                       const float* __restrict__ km, const float* __restrict__ Wk,
                       const float* __restrict__ bk,
                       const float* __restrict__ W1, const float* __restrict__ b1,
                       const float* __restrict__ W2, const float* __restrict__ b2,
                       const float* __restrict__ Wo, const float* __restrict__ bo) {
    __shared__ float stk[2500], qe[50], qu[50], lg[50], red[2];
    int b = blockIdx.x, tid = threadIdx.x;
    if (b < 1001) {
        int q = b;
        for (int i = tid; i < 2500; i += 256) {
            int m = i / 50, k = i % 50;
            float a = bk[m];
            for (int l = 0; l < 50; l++) a = fmaf(km[l * 50 + k], Wk[m * 50 + l], a);
            stk[i] = a;
        }
        if (tid < 50) qe[tid] = qet[q * 50 + tid];
        __syncthreads();
        if (tid < 50) {
            float a = bq[tid];
            for (int l = 0; l < 50; l++) a = fmaf(Wq[tid * 50 + l], qe[l], a);
            qu[tid] = tanhf(a);
        }
        __syncthreads();
        if (tid < 50) {
            float a = 0.f;
            for (int k = 0; k < 50; k++) a = fmaf(stk[tid * 50 + k], qu[k], a);
            lg[tid] = a;
        }
        __syncthreads();
        if (tid == 0) {
            float mx = -1e30f;
            for (int m = 0; m < 50; m++) mx = fmaxf(mx, lg[m]);
            float s = 0.f;
            for (int m = 0; m < 50; m++) s += expf(lg[m] - mx);
            red[0] = mx; red[1] = 1.f / s;
        }
        __syncthreads();
        if (tid < 52) {
            float v = (tid < 50) ? expf(lg[tid] - red[0]) * red[1] : 0.f;
            g_at2[q * 104 + 2 * tid]     = v;
            g_at2[q * 104 + 2 * tid + 1] = v;
        }
    } else if (b < 1393) {
        int idx = (b - 1001) * 256 + tid;
        if (idx < 1001 * 100) {
            int q = idx / 100, j = idx % 100;
            float a = b1[j];
            const float* w = W1 + j * 250 + 200;
            const float* e = qet + q * 50;
            for (int k = 0; k < 50; k++) a = fmaf(w[k], e[k], a);
            g_c1[idx] = a;
        }
    } else {
        int i = (b - 1393) * 256 + tid;
        if (i < 5000) {
            g_w2e[i] = W2[i];
        } else if (i < 5400) {
            int idx = i - 5000, c = idx / 100, k = idx % 100;
            float a = 0.f;
            for (int f = 0; f < 50; f++) a = fmaf(Wo[c * 50 + f], W2[f * 100 + k], a);
            g_w2e[i] = a;
        } else if (i < 5500) {
            int k = i - 5400;
            float a = 0.f;
            for (int f = 0; f < 50; f++) a += W2[f * 100 + k];
            g_w2e[i] = a * (1.f / 50.f);
        } else if (i < 5600) {
            g_w2e[i] = 0.f;
        } else if (i < 5656) {
            int j = i - 5600;
            float v = 0.f;
            if (j < 50) v = b2[j];
            else if (j < 54) {
                int c = j - 50;
                v = bo[c];
                for (int f = 0; f < 50; f++) v = fmaf(Wo[c * 50 + f], b2[f], v);
            } else if (j == 54) {
                float a = 0.f;
                for (int f = 0; f < 50; f++) a += b2[f];
                v = a * (1.f / 50.f);
            }
            g_b2e[j] = v;
        }
    }
}

// ================= prepC: erase/add GEMM, ve computed inline =================
__global__ void prepC(const float* __restrict__ We, const float* __restrict__ be,
                      const float* __restrict__ Wa, const float* __restrict__ ba,
                      const float* __restrict__ Wv, const float* __restrict__ bv) {
    __shared__ float As[16][64];
    __shared__ float Bs[16][64];
    int i0 = blockIdx.x * 64, j0 = blockIdx.y * 64;
    int tid = threadIdx.x;
    int ty = tid >> 4, tx = tid & 15;
    float acc[4][4] = {};
    for (int kb = 0; kb < 200; kb += 16) {
        for (int l = tid; l < 1024; l += 256) {
            // A tile: consecutive lanes -> consecutive gi (coalesced Wv)
            {
                int c = l >> 6, r = l & 63;
                int gi = i0 + r, gk = kb + c;
                float val = 0.f;
                if (gi < 4004 && gk < 200) {
                    int q = gi >> 2, rr = gi & 3;
                    val = bv[gk];
                    if (q > 0) {
#pragma unroll
                        for (int cc = 0; cc < 4; cc++) {
                            float w = 1.0f - fabsf((float)(cc - rr)) * (1.0f / 3.0f);
                            if (w > 0.0f)
                                val = fmaf(w, Wv[gk * 4000 + cc * 1000 + q - 1], val);
                        }
                    }
                }
                As[c][r] = val;
            }
            // B tile: consecutive lanes -> consecutive gk (coalesced We/Wa)
            {
                int r = l >> 4, c = l & 15;
                int gj = j0 + r, gk = kb + c;
                float bval = 0.f;
                if (gj < 400 && gk < 200)
                    bval = (gj < 200) ? We[gj * 200 + gk] : Wa[(gj - 200) * 200 + gk];
                Bs[c][r] = bval;
            }
        }
        __syncthreads();
#pragma unroll
        for (int k = 0; k < 16; k++) {
            float a[4], bb[4];
#pragma unroll
            for (int u = 0; u < 4; u++) a[u] = As[k][ty * 4 + u];
#pragma unroll
            for (int u = 0; u < 4; u++) bb[u] = Bs[k][tx * 4 + u];
#pragma unroll
            for (int u = 0; u < 4; u++)
#pragma unroll
                for (int v = 0; v < 4; v++) acc[u][v] = fmaf(a[u], bb[v], acc[u][v]);
        }
        __syncthreads();
    }
#pragma unroll
    for (int u = 0; u < 4; u++) {
        int gi = i0 + ty * 4 + u;
        if (gi >= 4004) break;
#pragma unroll
        for (int v = 0; v < 4; v++) {
            int gj = j0 + tx * 4 + v;
            if (gj >= 400) continue;
            float x = acc[u][v] + ((gj < 200) ? be[gj] : ba[gj - 200]);
            g_ea[(size_t)gi * 400 + gj] = (gj < 200) ? (1.0f / (1.0f + expf(-x))) : tanhf(x);
        }
    }
}

// ================= Phase 1: barrier-free Vm recurrence =================
#define TPB1 224
constexpr int G1 = 2;
constexpr int P1_SMF = 2000 + 7 * 2 * 208;   // 4912 floats

__global__ void __launch_bounds__(TPB1, 2)
phase1(const int* __restrict__ questions, const int* __restrict__ responses,
       const float* __restrict__ ivm) {
    __shared__ float sm[P1_SMF];
    int* qs = (int*)sm;
    int* rs = (int*)(sm + 1000);
    const int tid = threadIdx.x;
    const int wid = tid >> 5, lane = tid & 31;
    const int b0 = blockIdx.x * G1;

    for (int i = tid; i < G1 * S_; i += TPB1) {
        qs[i] = questions[b0 * S_ + i];
        rs[i] = responses[b0 * S_ + i];
    }

    const int cp = (tid < 200) ? tid : 199;
    const int g = cp / 100, p = cp % 100;

    ull vm[50];
#pragma unroll
    for (int m = 0; m < 50; m++) vm[m] = *(const ull*)(ivm + m * 200 + 2 * p);

    __syncthreads();   // only block barrier

    float* mybuf = sm + 2000 + wid * 416;
    const int* qsg = qs + g * S_;
    const int* rsg = rs + g * S_;

    for (int i = lane; i < 52; i += 32) {
        int gg = i / 26, j = i % 26;
        cp16(mybuf + gg * 104 + j * 4, g_at2 + qs[gg * S_] * 104 + j * 4);
    }
    asm volatile("cp.async.commit_group;\n" ::: "memory");

    ull eC, aC;
    {
        const float* eb = g_ea + (size_t)(qsg[0] * 4 + rsg[0]) * 400;
        eC = *(const ull*)(eb + 2 * p);
        aC = *(const ull*)(eb + 200 + 2 * p);
    }

    size_t hb = (size_t)(b0 + g) * (S_ * 200) + 2 * p;

    for (int t = 0; t < S_; t++) {
        ull eN = 0ull, aN = 0ull;
        if (t + 1 < S_) {
            const float* eb = g_ea + (size_t)(qsg[t + 1] * 4 + rsg[t + 1]) * 400;
            eN = *(const ull*)(eb + 2 * p);
            aN = *(const ull*)(eb + 200 + 2 * p);
            float* nb = mybuf + ((t + 1) & 1) * 208;
            for (int i = lane; i < 52; i += 32) {
                int gg = i / 26, j = i % 26;
                cp16(nb + gg * 104 + j * 4, g_at2 + qs[gg * S_ + t + 1] * 104 + j * 4);
            }
        }
        asm volatile("cp.async.commit_group;\n" ::: "memory");
        asm volatile("cp.async.wait_group 1;\n" ::: "memory");
        __syncwarp();

        const ulonglong2* at2p = (const ulonglong2*)(mybuf + (t & 1) * 208 + g * 104);
        ull en = eC ^ 0x8000000080000000ULL;
        ull ad = aC;
        ull ra = 0ull, rb = 0ull;
#pragma unroll
        for (int j2 = 0; j2 < 25; j2++) {
            ulonglong2 uu = at2p[j2];
            ull tt;
            FMA2(ra, uu.x, vm[2 * j2], ra);
            FMA2(tt, en, vm[2 * j2], ad);
            FMA2(vm[2 * j2], uu.x, tt, vm[2 * j2]);
            FMA2(rb, uu.y, vm[2 * j2 + 1], rb);
            FMA2(tt, en, vm[2 * j2 + 1], ad);
            FMA2(vm[2 * j2 + 1], uu.y, tt, vm[2 * j2 + 1]);
        }
        ull one2 = PK(1.0f, 1.0f), r2;
        FMA2(r2, rb, one2, ra);
        if (tid < 200)
            *(ull*)(g_h + hb + (size_t)t * 200) = r2;
        eC = eN; aC = aN;
    }
}

// ================= Phase 2: batched MLP over all (b,t) =================
#define TPB2 256
constexpr int HSTR = 204;
constexpr int H1STR = 102;
constexpr int O2_H   = 0;          // 64 x 204 = 13056
constexpr int O2_H1  = 13056;      // 64 x 102 = 6528
constexpr int O2_W2E = 19584;      // 56 x 100 = 5600
constexpr int O2_B2E = 25184;      // 56
constexpr int O2_LG  = 25240;      // 64 x 4 = 256
constexpr int O2_QN  = 25496;      // 64 int
constexpr int P2_SMF = 25560;      // 102,240 B

__global__ void __launch_bounds__(TPB2, 2)
phase2(const int* __restrict__ questions, const float* __restrict__ W1,
       float* __restrict__ outF, float* __restrict__ outM,
       float* __restrict__ outL, float* __restrict__ outP) {
    extern __shared__ float s2[];
    const int tid = threadIdx.x;
    const int n0 = blockIdx.x * 64;
    int* qn = (int*)(s2 + O2_QN);

    // ---- stage A: load h rows, W2e, b2e, question ids ----
    for (int i = tid; i < 3200; i += TPB2) {
        int r = i / 50, c = i % 50;
        cp16(s2 + O2_H + r * HSTR + c * 4, g_h + (size_t)(n0 + r) * 200 + c * 4);
    }
    for (int i = tid; i < 1400; i += TPB2)
        cp16(s2 + O2_W2E + i * 4, g_w2e + i * 4);
    if (tid < 14) cp16(s2 + O2_B2E + tid * 4, g_b2e + tid * 4);
    if (tid < 64) qn[tid] = questions[n0 + tid];
    asm volatile("cp.async.commit_group;\n" ::: "memory");
    asm volatile("cp.async.wait_group 0;\n" ::: "memory");
    __syncthreads();

    // ---- stage B: h1 = relu(W1[:, :200] @ h + c1[q]), 4j x 8rows ----
    if (tid < 200) {
        int jg = tid / 8, rg = tid % 8;
        int j0 = jg * 4;
        ull acc[4][8] = {};
        for (int k = 0; k < 200; k += 2) {
            ull h[8];
#pragma unroll
            for (int i = 0; i < 8; i++)
                h[i] = *(const ull*)(s2 + O2_H + (rg + 8 * i) * HSTR + k);
#pragma unroll
            for (int j = 0; j < 4; j++) {
                ull w = *(const ull*)(W1 + (j0 + j) * 250 + k);
#pragma unroll
                for (int i = 0; i < 8; i++) FMA2(acc[j][i], w, h[i], acc[j][i]);
            }
        }
#pragma unroll
        for (int j = 0; j < 4; j++)
#pragma unroll
            for (int i = 0; i < 8; i++) {
                int row = rg + 8 * i;
                float v = HADD(acc[j][i]) + g_c1[qn[row] * 100 + j0 + j];
                s2[O2_H1 + row * H1STR + j0 + j] = fmaxf(v, 0.f);
            }
    }
    __syncthreads();

    // ---- stage C: W2e(56 x 100) @ h1 -> feats + logits + mastery, 2f x 8r ----
    if (tid < 224) {
        int fg = tid >> 3, rg = tid & 7;   // fg 0..27, rg 0..7
        int f0 = fg * 2;
        ull acc[2][8] = {};
#pragma unroll 5
        for (int kk = 0; kk < 50; kk++) {
            ull h1v[8];
#pragma unroll
            for (int i = 0; i < 8; i++)
                h1v[i] = *(const ull*)(s2 + O2_H1 + (rg + 8 * i) * H1STR + 2 * kk);
            ull w0 = *(const ull*)(s2 + O2_W2E + f0 * 100 + 2 * kk);
            ull w1 = *(const ull*)(s2 + O2_W2E + (f0 + 1) * 100 + 2 * kk);
#pragma unroll
            for (int i = 0; i < 8; i++) {
                FMA2(acc[0][i], w0, h1v[i], acc[0][i]);
                FMA2(acc[1][i], w1, h1v[i], acc[1][i]);
            }
        }
#pragma unroll
        for (int j = 0; j < 2; j++) {
            int f = f0 + j;
            if (f >= 55) continue;
            float bias = s2[O2_B2E + f];
#pragma unroll
            for (int i = 0; i < 8; i++) {
                int row = rg + 8 * i;
                float val = HADD(acc[j][i]) + bias;
                if (f < 50)      outF[(size_t)(n0 + row) * 50 + f] = val;
                else if (f < 54) s2[O2_LG + row * 4 + (f - 50)] = val;
                else             outM[n0 + row] = val;
            }
        }
    }
    __syncthreads();

    // ---- softmax over logits ----
    {
        int row = tid >> 2, c = tid & 3;
        float lg = s2[O2_LG + row * 4 + c];
        float mx = fmaxf(lg, __shfl_xor_sync(0xffffffffu, lg, 1));
        mx = fmaxf(mx, __shfl_xor_sync(0xffffffffu, mx, 2));
        float e = expf(lg - mx);
        float se = e + __shfl_xor_sync(0xffffffffu, e, 1);
        se += __shfl_xor_sync(0xffffffffu, se, 2);
        size_t o = (size_t)(n0 + row) * 4 + c;
        outL[o] = lg;
        outP[o] = e / se;
    }
}

// ---------------------------------------------------------------------------

extern "C" void kernel_launch(void* const* d_in, const int* in_sizes, int n_in,
                              void* d_out, int out_size) {
    const int*   questions = (const int*)d_in[0];
    const int*   responses = (const int*)d_in[1];
    const float* qet       = (const float*)d_in[2];
    const float* Wv        = (const float*)d_in[3];
    const float* bv        = (const float*)d_in[4];
    const float* km        = (const float*)d_in[5];
    const float* ivm       = (const float*)d_in[6];
    const float* Wq        = (const float*)d_in[7];
    const float* bq        = (const float*)d_in[8];
    const float* Wk        = (const float*)d_in[9];
    const float* bk        = (const float*)d_in[10];
    const float* We        = (const float*)d_in[11];
    const float* be        = (const float*)d_in[12];
    const float* Wa        = (const float*)d_in[13];
    const float* ba        = (const float*)d_in[14];
    const float* W1        = (const float*)d_in[15];
    const float* b1        = (const float*)d_in[16];
    const float* W2        = (const float*)d_in[17];
    const float* b2        = (const float*)d_in[18];
    const float* Wo        = (const float*)d_in[19];
    const float* bo        = (const float*)d_in[20];

    float* out  = (float*)d_out;
    float* outF = out;
    float* outM = out + (size_t)512 * 500 * 50;
    float* outL = outM + (size_t)512 * 500;
    float* outP = outL + (size_t)512 * 500 * 4;

    cudaFuncSetAttribute(phase2, cudaFuncAttributeMaxDynamicSharedMemorySize,
                         P2_SMF * 4);

    prepBF<<<1416, 256>>>(qet, Wq, bq, km, Wk, bk, W1, b1, W2, b2, Wo, bo);
    {
        dim3 grid(63, 7);
        prepC<<<grid, 256>>>(We, be, Wa, ba, Wv, bv);
    }
    phase1<<<512 / G1, TPB1>>>(questions, responses, ivm);
    phase2<<<4000, TPB2, P2_SMF * 4>>>(questions, W1, outF, outM, outL, outP);
}